// round 4
// baseline (speedup 1.0000x reference)
#include <cuda_runtime.h>

#define NROWS 8192
#define NDIM  512
#define ND4   128      // NDIM/4
#define NTOP  100
#define NBLK  128
#define NTHR  256

__device__ float4 g_spart[NBLK][ND4];
__device__ float4 g_s4v[ND4];
__device__ unsigned int g_key[NROWS];
__device__ int    g_rank2row[NTOP];
__device__ volatile unsigned int g_bar[5];   // [0..3] phase barriers, [4] done ctr

// Grid-wide barrier: release-fence by all threads, elected arrive + spin.
__device__ __forceinline__ void gridbar(int i) {
    __threadfence();
    __syncthreads();
    if (threadIdx.x == 0) {
        atomicAdd((unsigned int*)&g_bar[i], 1u);
        while (g_bar[i] < NBLK) __nanosleep(64);
    }
    __syncthreads();
}

__global__ void __launch_bounds__(NTHR, 1) kFused(const float4* __restrict__ x4,
                                                  float* __restrict__ out,
                                                  float4* __restrict__ out4,
                                                  int out_size) {
    __shared__ union {
        struct { float4 sacc[8][ND4]; } p1;                      // 16 KB
        float4 p2red[128];                                       // 2 KB
        float4 s4[ND4];                                          // 2 KB
        struct { unsigned int keys[NROWS];
                 int hist[256];
                 unsigned int ckey[256];
                 int cidx[256]; } p4;                            // ~35 KB
    } sh;
    __shared__ unsigned int sh_prefix;
    __shared__ int sh_needed, sh_ncand;

    const int t    = threadIdx.x;
    const int wid  = t >> 5;
    const int lane = t & 31;
    const int gw   = blockIdx.x * 8 + wid;     // 1024 warps, 8 rows each

    // ===== P1: per-row 1/||x|| (kept in regs) + column-sum of unit rows =====
    float rinvs[8];
    {
        float4 acc[4];
        #pragma unroll
        for (int k = 0; k < 4; ++k) acc[k] = make_float4(0.f, 0.f, 0.f, 0.f);

        #pragma unroll
        for (int r = 0; r < 8; ++r) {
            int row = gw * 8 + r;
            const float4* xr = x4 + (size_t)row * ND4;
            float4 v[4];
            #pragma unroll
            for (int k = 0; k < 4; ++k) v[k] = xr[lane + 32 * k];

            float sq = 0.f;
            #pragma unroll
            for (int k = 0; k < 4; ++k)
                sq += v[k].x*v[k].x + v[k].y*v[k].y + v[k].z*v[k].z + v[k].w*v[k].w;
            #pragma unroll
            for (int o = 16; o; o >>= 1) sq += __shfl_xor_sync(0xffffffffu, sq, o);

            float rinv = rsqrtf(sq);
            rinv = rinv * (1.5f - 0.5f * sq * rinv * rinv);   // Newton refine
            rinvs[r] = rinv;

            #pragma unroll
            for (int k = 0; k < 4; ++k) {
                acc[k].x = fmaf(v[k].x, rinv, acc[k].x);
                acc[k].y = fmaf(v[k].y, rinv, acc[k].y);
                acc[k].z = fmaf(v[k].z, rinv, acc[k].z);
                acc[k].w = fmaf(v[k].w, rinv, acc[k].w);
            }
        }
        #pragma unroll
        for (int k = 0; k < 4; ++k) sh.p1.sacc[wid][lane + 32 * k] = acc[k];
        __syncthreads();

        if (t < ND4) {
            float4 s = sh.p1.sacc[0][t];
            #pragma unroll
            for (int w = 1; w < 8; ++w) {
                float4 v = sh.p1.sacc[w][t];
                s.x += v.x; s.y += v.y; s.z += v.z; s.w += v.w;
            }
            g_spart[blockIdx.x][t] = s;
        }
    }
    gridbar(0);

    // ===== P2: block b reduces float4-dim b across 128 partials =====
    {
        int b = blockIdx.x;                    // NBLK == ND4
        if (t < 128) sh.p2red[t] = g_spart[t][b];
        __syncthreads();
        #pragma unroll
        for (int s = 64; s > 0; s >>= 1) {
            if (t < s) {
                float4 a = sh.p2red[t], c = sh.p2red[t + s];
                a.x += c.x; a.y += c.y; a.z += c.z; a.w += c.w;
                sh.p2red[t] = a;
            }
            __syncthreads();
        }
        if (t == 0) g_s4v[b] = sh.p2red[0];
    }
    gridbar(1);

    // ===== P3: scores (x is L2-hot), order-preserving u32 keys =====
    {
        if (t < ND4) sh.s4[t] = g_s4v[t];
        __syncthreads();
        #pragma unroll
        for (int r = 0; r < 8; ++r) {
            int row = gw * 8 + r;
            const float4* xr = x4 + (size_t)row * ND4;
            float dot = 0.f;
            #pragma unroll
            for (int k = 0; k < 4; ++k) {
                float4 v = xr[lane + 32 * k];
                float4 s = sh.s4[lane + 32 * k];
                dot = fmaf(v.x, s.x, dot);
                dot = fmaf(v.y, s.y, dot);
                dot = fmaf(v.z, s.z, dot);
                dot = fmaf(v.w, s.w, dot);
            }
            #pragma unroll
            for (int o = 16; o; o >>= 1) dot += __shfl_down_sync(0xffffffffu, dot, o);
            if (lane == 0) {
                float score = dot * rinvs[r];
                unsigned int u = __float_as_uint(score);
                u = (u & 0x80000000u) ? ~u : (u | 0x80000000u);
                g_key[row] = u;
            }
        }
    }
    gridbar(2);

    // ===== P4: block 0 — MSB-first radix select + exact stable ranks =====
    if (blockIdx.x == 0) {
        #pragma unroll
        for (int j = 0; j < 32; ++j) sh.p4.keys[t + NTHR * j] = g_key[t + NTHR * j];
        if (t == 0) sh_ncand = 0;
        __syncthreads();

        unsigned int prefix = 0;
        int needed = NTOP;
        #pragma unroll
        for (int round = 0; round < 4; ++round) {
            const int shift = 24 - 8 * round;
            if (t < 256) sh.p4.hist[t] = 0;
            __syncthreads();

            for (int j = 0; j < 32; ++j) {
                unsigned int k = sh.p4.keys[t + NTHR * j];
                bool ok = (round == 0) ? true : ((k >> (shift + 8)) == prefix);
                unsigned int active = __ballot_sync(0xffffffffu, ok);
                if (ok) {
                    int bin = (k >> shift) & 0xFF;
                    unsigned int same = __match_any_sync(active, bin);
                    if (lane == __ffs(same) - 1)
                        atomicAdd(&sh.p4.hist[bin], __popc(same));
                }
            }
            __syncthreads();

            if (t < 32) {
                int local[8]; int lsum = 0;
                #pragma unroll
                for (int i = 0; i < 8; ++i) { local[i] = sh.p4.hist[t * 8 + i]; lsum += local[i]; }
                int v = lsum;
                #pragma unroll
                for (int o = 1; o < 32; o <<= 1) {
                    int u = __shfl_up_sync(0xffffffffu, v, o);
                    if (lane >= o) v += u;
                }
                int run = v - lsum;
                #pragma unroll
                for (int i = 0; i < 8; ++i) {
                    if (run < needed && needed <= run + local[i]) {
                        sh_prefix = (prefix << 8) | (unsigned int)(t * 8 + i);
                        sh_needed = needed - run;
                    }
                    run += local[i];
                }
            }
            __syncthreads();
            prefix = sh_prefix;
            needed = sh_needed;
            __syncthreads();
        }
        unsigned int kth = prefix;   // exact 100th-smallest key

        for (int j = 0; j < 32; ++j) {
            int i = t + NTHR * j;
            unsigned int k = sh.p4.keys[i];
            if (k <= kth) {
                int p = atomicAdd(&sh_ncand, 1);
                if (p < 256) { sh.p4.ckey[p] = k; sh.p4.cidx[p] = i; }
            }
        }
        __syncthreads();
        int nc = sh_ncand < 256 ? sh_ncand : 256;

        if (t < nc) {
            unsigned int mk = sh.p4.ckey[t];
            int mi = sh.p4.cidx[t];
            int rank = 0;
            for (int j = 0; j < nc; ++j)
                rank += (sh.p4.ckey[j] < mk ||
                         (sh.p4.ckey[j] == mk && sh.p4.cidx[j] < mi)) ? 1 : 0;
            if (rank < NTOP) {
                g_rank2row[rank] = mi;
                if (NTOP * NDIM + rank < out_size)
                    out[NTOP * NDIM + rank] = (float)mi;
            }
        }
    }
    gridbar(3);

    // ===== P5: blocks 0..99 gather one selected row each =====
    if (blockIdx.x < NTOP && t < ND4) {
        int row = g_rank2row[blockIdx.x];
        int e = blockIdx.x * ND4 + t;
        if (4 * e + 4 <= out_size)
            out4[e] = x4[(size_t)row * ND4 + t];
    }

    // ===== epilogue: last block to finish resets barrier state =====
    __syncthreads();
    if (t == 0) {
        __threadfence();
        if (atomicAdd((unsigned int*)&g_bar[4], 1u) == NBLK - 1) {
            g_bar[0] = 0; g_bar[1] = 0; g_bar[2] = 0; g_bar[3] = 0; g_bar[4] = 0;
            __threadfence();
        }
    }
}

extern "C" void kernel_launch(void* const* d_in, const int* in_sizes, int n_in,
                              void* d_out, int out_size) {
    const float4* x4 = (const float4*)d_in[0];
    kFused<<<NBLK, NTHR>>>(x4, (float*)d_out, (float4*)d_out, out_size);
}

// round 5
// speedup vs baseline: 1.3113x; 1.3113x over previous
#include <cuda_runtime.h>

#define NROWS 8192
#define NDIM  512
#define ND4   128      // NDIM/4
#define NTOP  100
#define NBLK  128
#define NTHR  1024

__device__ float4 g_spart[NBLK][ND4];
__device__ unsigned int g_key[NROWS];
__device__ int    g_rank2row[NTOP];
__device__ volatile unsigned int g_bar[4];   // [0..2] phase barriers, [3] done ctr

__device__ __forceinline__ void gridbar(int i) {
    __threadfence();
    __syncthreads();
    if (threadIdx.x == 0) {
        atomicAdd((unsigned int*)&g_bar[i], 1u);
        while (g_bar[i] < NBLK) __nanosleep(32);
    }
    __syncthreads();
}

__global__ void __launch_bounds__(NTHR, 1) kFused(const float4* __restrict__ x4,
                                                  float* __restrict__ out,
                                                  float4* __restrict__ out4,
                                                  int out_size) {
    __shared__ union {
        float4 sacc[16][ND4];                                    // 32 KB (P1)
        struct { float4 sred[8][ND4]; float4 s4[ND4]; } p3;      // 18 KB
        struct { int hist[256]; unsigned int ckey[256];
                 int cidx[256]; } p4;                            // 3 KB
    } sh;
    __shared__ unsigned int sh_prefix;
    __shared__ int sh_needed, sh_ncand;

    const int t    = threadIdx.x;
    const int wid  = t >> 5;          // 0..31
    const int lane = t & 31;

    // ===== P1: per-row 1/||x|| (regs) + column-sum of unit rows =====
    // Block owns 64 contiguous rows; each warp 2 rows.
    float rinvs[2];
    {
        float4 acc[4];
        #pragma unroll
        for (int k = 0; k < 4; ++k) acc[k] = make_float4(0.f, 0.f, 0.f, 0.f);

        #pragma unroll
        for (int r = 0; r < 2; ++r) {
            int row = blockIdx.x * 64 + wid * 2 + r;
            const float4* xr = x4 + (size_t)row * ND4;
            float4 v[4];
            #pragma unroll
            for (int k = 0; k < 4; ++k) v[k] = xr[lane + 32 * k];

            float sq = 0.f;
            #pragma unroll
            for (int k = 0; k < 4; ++k)
                sq += v[k].x*v[k].x + v[k].y*v[k].y + v[k].z*v[k].z + v[k].w*v[k].w;
            #pragma unroll
            for (int o = 16; o; o >>= 1) sq += __shfl_xor_sync(0xffffffffu, sq, o);

            float rinv = rsqrtf(sq);
            rinv = rinv * (1.5f - 0.5f * sq * rinv * rinv);   // Newton refine
            rinvs[r] = rinv;

            #pragma unroll
            for (int k = 0; k < 4; ++k) {
                acc[k].x = fmaf(v[k].x, rinv, acc[k].x);
                acc[k].y = fmaf(v[k].y, rinv, acc[k].y);
                acc[k].z = fmaf(v[k].z, rinv, acc[k].z);
                acc[k].w = fmaf(v[k].w, rinv, acc[k].w);
            }
        }
        // 32 warps -> 16 smem buffers -> 1
        if (wid >= 16) {
            #pragma unroll
            for (int k = 0; k < 4; ++k) sh.sacc[wid - 16][lane + 32 * k] = acc[k];
        }
        __syncthreads();
        if (wid < 16) {
            #pragma unroll
            for (int k = 0; k < 4; ++k) {
                float4 o = sh.sacc[wid][lane + 32 * k];
                acc[k].x += o.x; acc[k].y += o.y; acc[k].z += o.z; acc[k].w += o.w;
                sh.sacc[wid][lane + 32 * k] = acc[k];
            }
        }
        __syncthreads();
        if (t < ND4) {
            float4 s = sh.sacc[0][t];
            #pragma unroll
            for (int w = 1; w < 16; ++w) {
                float4 v = sh.sacc[w][t];
                s.x += v.x; s.y += v.y; s.z += v.z; s.w += v.w;
            }
            g_spart[blockIdx.x][t] = s;
        }
    }
    gridbar(0);

    // ===== P3: each block reduces s itself (L2 reads), then scores =====
    {
        int d = t & (ND4 - 1);
        int q = t >> 7;                 // 0..7, 16 partials each
        float4 s = make_float4(0.f, 0.f, 0.f, 0.f);
        #pragma unroll 4
        for (int p = q * 16; p < (q + 1) * 16; ++p) {
            float4 v = g_spart[p][d];
            s.x += v.x; s.y += v.y; s.z += v.z; s.w += v.w;
        }
        sh.p3.sred[q][d] = s;
        __syncthreads();
        if (t < ND4) {
            float4 a = sh.p3.sred[0][t];
            #pragma unroll
            for (int w = 1; w < 8; ++w) {
                float4 v = sh.p3.sred[w][t];
                a.x += v.x; a.y += v.y; a.z += v.z; a.w += v.w;
            }
            sh.p3.s4[t] = a;
        }
        __syncthreads();

        #pragma unroll
        for (int r = 0; r < 2; ++r) {
            int row = blockIdx.x * 64 + wid * 2 + r;
            const float4* xr = x4 + (size_t)row * ND4;
            float dot = 0.f;
            #pragma unroll
            for (int k = 0; k < 4; ++k) {
                float4 v = xr[lane + 32 * k];
                float4 sv = sh.p3.s4[lane + 32 * k];
                dot = fmaf(v.x, sv.x, dot);
                dot = fmaf(v.y, sv.y, dot);
                dot = fmaf(v.z, sv.z, dot);
                dot = fmaf(v.w, sv.w, dot);
            }
            #pragma unroll
            for (int o = 16; o; o >>= 1) dot += __shfl_down_sync(0xffffffffu, dot, o);
            if (lane == 0) {
                float score = dot * rinvs[r];
                unsigned int u = __float_as_uint(score);
                u = (u & 0x80000000u) ? ~u : (u | 0x80000000u);
                g_key[row] = u;
            }
        }
    }
    gridbar(1);

    // ===== P4: block 0 — MSB-first radix select, 8 register keys/thread =====
    if (blockIdx.x == 0) {
        unsigned int k[8];
        #pragma unroll
        for (int j = 0; j < 8; ++j) k[j] = g_key[t + NTHR * j];
        if (t == 0) sh_ncand = 0;

        unsigned int prefix = 0;
        int needed = NTOP;
        #pragma unroll
        for (int round = 0; round < 4; ++round) {
            const int shift = 24 - 8 * round;
            if (t < 256) sh.p4.hist[t] = 0;
            __syncthreads();

            #pragma unroll
            for (int j = 0; j < 8; ++j) {
                bool ok = (round == 0) ? true : ((k[j] >> (shift + 8)) == prefix);
                unsigned int active = __ballot_sync(0xffffffffu, ok);
                if (ok) {
                    int bin = (k[j] >> shift) & 0xFF;
                    unsigned int same = __match_any_sync(active, bin);
                    if (lane == __ffs(same) - 1)
                        atomicAdd(&sh.p4.hist[bin], __popc(same));
                }
            }
            __syncthreads();

            if (t < 32) {
                int local[8]; int lsum = 0;
                #pragma unroll
                for (int i = 0; i < 8; ++i) { local[i] = sh.p4.hist[t * 8 + i]; lsum += local[i]; }
                int v = lsum;
                #pragma unroll
                for (int o = 1; o < 32; o <<= 1) {
                    int u = __shfl_up_sync(0xffffffffu, v, o);
                    if (lane >= o) v += u;
                }
                int run = v - lsum;
                #pragma unroll
                for (int i = 0; i < 8; ++i) {
                    if (run < needed && needed <= run + local[i]) {
                        sh_prefix = (prefix << 8) | (unsigned int)(t * 8 + i);
                        sh_needed = needed - run;
                    }
                    run += local[i];
                }
            }
            __syncthreads();
            prefix = sh_prefix;
            needed = sh_needed;
            __syncthreads();
        }
        unsigned int kth = prefix;   // exact 100th-smallest key

        #pragma unroll
        for (int j = 0; j < 8; ++j) {
            if (k[j] <= kth) {
                int p = atomicAdd(&sh_ncand, 1);
                if (p < 256) { sh.p4.ckey[p] = k[j]; sh.p4.cidx[p] = t + NTHR * j; }
            }
        }
        __syncthreads();
        int nc = sh_ncand < 256 ? sh_ncand : 256;

        if (t < nc) {
            unsigned int mk = sh.p4.ckey[t];
            int mi = sh.p4.cidx[t];
            int rank = 0;
            for (int j = 0; j < nc; ++j)
                rank += (sh.p4.ckey[j] < mk ||
                         (sh.p4.ckey[j] == mk && sh.p4.cidx[j] < mi)) ? 1 : 0;
            if (rank < NTOP) {
                g_rank2row[rank] = mi;
                if (NTOP * NDIM + rank < out_size)
                    out[NTOP * NDIM + rank] = (float)mi;
            }
        }
    }
    gridbar(2);

    // ===== P5: blocks 0..99 gather one selected row each =====
    if (blockIdx.x < NTOP && t < ND4) {
        int row = g_rank2row[blockIdx.x];
        int e = blockIdx.x * ND4 + t;
        if (4 * e + 4 <= out_size)
            out4[e] = x4[(size_t)row * ND4 + t];
    }

    // ===== epilogue: last block resets barrier state (post-all-spins) =====
    __syncthreads();
    if (t == 0) {
        __threadfence();
        if (atomicAdd((unsigned int*)&g_bar[3], 1u) == NBLK - 1) {
            g_bar[0] = 0; g_bar[1] = 0; g_bar[2] = 0; g_bar[3] = 0;
            __threadfence();
        }
    }
}

extern "C" void kernel_launch(void* const* d_in, const int* in_sizes, int n_in,
                              void* d_out, int out_size) {
    const float4* x4 = (const float4*)d_in[0];
    kFused<<<NBLK, NTHR>>>(x4, (float*)d_out, (float4*)d_out, out_size);
}